// round 17
// baseline (speedup 1.0000x reference)
#include <cuda_runtime.h>
#include <math.h>

#define NQ    6
#define BATCH 256
#define HID   256
#define INP   784
#define KS    8
#define LAM1  0.9986666666666667f
#define LAM2  0.9866666666666667f
#define LAM12 (LAM1*LAM2)
#define PI_F  3.14159265358979323846f
#define NPTM  6
#define GEMM_BLOCKS 128
#define SMEM_DYN 51200

typedef unsigned long long u64;

__device__ float g_hp[KS * BATCH * HID];   // K-split partial GEMM outputs (2MB)
__device__ float g_Tct[768 * 8];           // evolved observables, [term][obs] zero-padded

// ---------- compile-time tables ----------
struct alignas(16) Tabs {
    short ring[3][4096];   // signed permutation: tg | neg<<12
    short s4of[736];       // base-3 index -> base-4 Pauli index (1->X, 2->Z), padded
};

static constexpr unsigned char LUTc[16] = {0,4,11,15, 5,1,14,26, 6,2,29,9, 3,7,8,12};

static constexpr Tabs make_tabs() {
    Tabs T = {};
    for (int r = 1; r <= 3; r++) {
        for (int s = 0; s < 4096; s++) {
            int cur = s, neg = 0;
            for (int i = 5; i >= 0; --i) {
                int c = i, t = (i + r) % 6;
                int a = (cur >> (2*c)) & 3, b = (cur >> (2*t)) & 3;
                int lv = LUTc[a*4 + b];
                cur = (cur & ~((3 << (2*c)) | (3 << (2*t))))
                    | ((lv & 3) << (2*c)) | (((lv >> 2) & 3) << (2*t));
                neg ^= lv >> 4;
            }
            T.ring[r-1][s] = (short)(cur | (neg << 12));
        }
    }
    for (int s = 0; s < 729; s++) {
        int tmp = s, s4 = 0;
        for (int q = 0; q < 6; q++) {
            int dd = tmp % 3; tmp /= 3;
            if (dd == 1) s4 |= 1 << (2*q);
            else if (dd == 2) s4 |= 3 << (2*q);
        }
        T.s4of[s] = (short)s4;
    }
    return T;
}
__device__ constexpr Tabs g_tabs = make_tabs();

__device__ __forceinline__ int PHYS(int s) {
    return s ^ (((s >> 4) & 7) << 2) ^ (((s >> 8) & 1) << 4);
}

__device__ __forceinline__ void ffma2(u64& d, u64 a, u64 b) {
    asm("fma.rn.f32x2 %0, %1, %2, %0;" : "+l"(d) : "l"(a), "l"(b));
}

// ---------- PTM passes ----------
__device__ __forceinline__ void rotAB(float* m, const float* A0, const float* A1, int tid)
{
    float4* m4 = reinterpret_cast<float4*>(m);
    const int P = (tid & 7) ^ (((tid >> 4) & 1) << 2);
    float4 v[4];
#pragma unroll
    for (int j = 0; j < 4; j++) v[j] = m4[(4*tid + j) ^ P];
#pragma unroll
    for (int j = 0; j < 4; j++) {
        float x = v[j].y, y = v[j].z, z = v[j].w;
        v[j].y = A0[0]*x + A0[1]*y + A0[2]*z;
        v[j].z = A0[3]*x + A0[4]*y + A0[5]*z;
        v[j].w = A0[6]*x + A0[7]*y + A0[8]*z;
    }
    {
        float4 a = v[1], b = v[2], c = v[3];
        v[1].x = A1[0]*a.x + A1[1]*b.x + A1[2]*c.x;
        v[1].y = A1[0]*a.y + A1[1]*b.y + A1[2]*c.y;
        v[1].z = A1[0]*a.z + A1[1]*b.z + A1[2]*c.z;
        v[1].w = A1[0]*a.w + A1[1]*b.w + A1[2]*c.w;
        v[2].x = A1[3]*a.x + A1[4]*b.x + A1[5]*c.x;
        v[2].y = A1[3]*a.y + A1[4]*b.y + A1[5]*c.y;
        v[2].z = A1[3]*a.z + A1[4]*b.z + A1[5]*c.z;
        v[2].w = A1[3]*a.w + A1[4]*b.w + A1[5]*c.w;
        v[3].x = A1[6]*a.x + A1[7]*b.x + A1[8]*c.x;
        v[3].y = A1[6]*a.y + A1[7]*b.y + A1[8]*c.y;
        v[3].z = A1[6]*a.z + A1[7]*b.z + A1[8]*c.z;
        v[3].w = A1[6]*a.w + A1[7]*b.w + A1[8]*c.w;
    }
#pragma unroll
    for (int j = 0; j < 4; j++) m4[(4*tid + j) ^ P] = v[j];
    __syncthreads();
}

__device__ __forceinline__ void rot2dig(float v[16], const float* Alo, const float* Ahi)
{
#pragma unroll
    for (int g = 0; g < 4; g++) {
        float x = v[g*4+1], y = v[g*4+2], z = v[g*4+3];
        v[g*4+1] = Alo[0]*x + Alo[1]*y + Alo[2]*z;
        v[g*4+2] = Alo[3]*x + Alo[4]*y + Alo[5]*z;
        v[g*4+3] = Alo[6]*x + Alo[7]*y + Alo[8]*z;
    }
#pragma unroll
    for (int c = 0; c < 4; c++) {
        float x = v[c+4], y = v[c+8], z = v[c+12];
        v[c+4]  = Ahi[0]*x + Ahi[1]*y + Ahi[2]*z;
        v[c+8]  = Ahi[3]*x + Ahi[4]*y + Ahi[5]*z;
        v[c+12] = Ahi[6]*x + Ahi[7]*y + Ahi[8]*z;
    }
}

__device__ __forceinline__ void rotCD(float* m, const float* A2, const float* A3, int tid)
{
    const int lo = tid & 15, hi = (tid >> 4) << 8;
    float v[16];
#pragma unroll
    for (int e = 0; e < 16; e++) v[e] = m[PHYS(hi | (e << 4) | lo)];
    rot2dig(v, A2, A3);
#pragma unroll
    for (int e = 0; e < 16; e++) m[PHYS(hi | (e << 4) | lo)] = v[e];
    __syncthreads();
}

__device__ __forceinline__ void rotEF(float* m, const float* A4, const float* A5, int tid,
                                      const short* ring, bool dep)
{
    float v[16];
#pragma unroll
    for (int e = 0; e < 16; e++) v[e] = m[PHYS((e << 8) | tid)];
    rot2dig(v, A4, A5);
    if (ring) {
        __syncthreads();
#pragma unroll
        for (int e = 0; e < 16; e++) {
            int s = (e << 8) | tid;
            float val = v[e];
            if (dep) {
                float sc = 1.f;
#pragma unroll
                for (int q = 0; q < 6; q++)
                    if ((s >> (2*q)) & 3) sc *= (q < 5) ? LAM12 : LAM1;
                val *= sc;
            }
            int tg = ring[s];
            m[PHYS(tg & 4095)] = (tg & 4096) ? -val : val;
        }
    } else {
#pragma unroll
        for (int e = 0; e < 16; e++) m[PHYS((e << 8) | tid)] = v[e];
    }
    __syncthreads();
}

// ---------- kernel 1: PTM evolution (blocks 0..5) + 64x64 f32x2 GEMM (6..133) ----------
__global__ void __launch_bounds__(256) k1(const float* __restrict__ x, const float* __restrict__ W1,
                                          const float* __restrict__ sw, const float* __restrict__ tw)
{
    extern __shared__ __align__(16) char su[];
    __shared__ float Mq[6][4];
    __shared__ int sTg;
    const int tid = threadIdx.x;
    const int blk = blockIdx.x;
    const int lane = tid & 31, wrp = tid >> 5;

    if (blk < NPTM) {
        float* m = reinterpret_cast<float*>(su);
        short* rtab = reinterpret_cast<short*>(su + 16384);             // [3][4096]
        float (*mats)[10] = reinterpret_cast<float(*)[10]>(su + 41216); // [30][10]

        {
            const uint4* srcT = reinterpret_cast<const uint4*>(&g_tabs.ring[0][0]);
            uint4* dstT = reinterpret_cast<uint4*>(rtab);
#pragma unroll
            for (int i = 0; i < 6; i++) dstT[tid + i*256] = srcT[tid + i*256];
        }
        if (tid < 30) {
            const float* wsrc = (tid < 18) ? (sw + tid*3) : (tw + (tid - 18)*3);
            float sp, cp, st, ct, sw_, cw_;
            sincosf(wsrc[0], &sp, &cp);
            sincosf(wsrc[1], &st, &ct);
            sincosf(wsrc[2], &sw_, &cw_);
            mats[tid][0] =  cp*ct*cw_ - sp*sw_;
            mats[tid][1] =  cp*ct*sw_ + sp*cw_;
            mats[tid][2] = -cp*st;
            mats[tid][3] = -sp*ct*cw_ - cp*sw_;
            mats[tid][4] = -sp*ct*sw_ + cp*cw_;
            mats[tid][5] =  sp*st;
            mats[tid][6] =  st*cw_;
            mats[tid][7] =  st*sw_;
            mats[tid][8] =  ct;
        }
        const int k = blk;
        if (tid == 0) sTg = g_tabs.ring[1][3 << (2*k)];   // first ring (r=2) analytic
        __syncthreads();

        const int tg0 = sTg;
        if (tid < 24) {
            int q = tid >> 2, j = tid & 3;
            int Pq = (tg0 >> (2*q)) & 3;
            float val;
            if (Pq == 0) val = (j == 0) ? 1.f : 0.f;
            else         val = (j == 0) ? 0.f : mats[24 + q][3*(j-1) + (Pq-1)];
            if (q == 0) val *= (tg0 & 4096) ? -LAM1 : LAM1;
            Mq[q][j] = val;
        }
        __syncthreads();

        // fused: materialize product state AND ring R1 scatter (bijection: no pre-zero)
        {
            float base = Mq[0][tid & 3] * Mq[1][(tid >> 2) & 3]
                       * Mq[2][(tid >> 4) & 3] * Mq[3][(tid >> 6) & 3];
            float m4v[4], m5v[4];
#pragma unroll
            for (int j = 0; j < 4; j++) { m4v[j] = Mq[4][j]; m5v[j] = Mq[5][j]; }
            const short* r1 = rtab;
#pragma unroll
            for (int e = 0; e < 16; e++) {
                int s = (e << 8) | tid;
                float val = base * m4v[e & 3] * m5v[e >> 2];
                int tg = r1[s];
                m[PHYS(tg & 4095)] = (tg & 4096) ? -val : val;
            }
        }
        __syncthreads();

        rotAB(m, mats[18], mats[19], tid);
        rotCD(m, mats[20], mats[21], tid);
        rotEF(m, mats[22], mats[23], tid, rtab + 2*4096, true);    // + dep + R3
        rotAB(m, mats[12], mats[13], tid);
        rotCD(m, mats[14], mats[15], tid);
        rotEF(m, mats[16], mats[17], tid, rtab + 1*4096, false);   // + R2
        rotAB(m, mats[6],  mats[7],  tid);
        rotCD(m, mats[8],  mats[9],  tid);
        rotEF(m, mats[10], mats[11], tid, rtab + 0*4096, false);   // + R1
        rotAB(m, mats[0],  mats[1],  tid);
        rotCD(m, mats[2],  mats[3],  tid);
        rotEF(m, mats[4],  mats[5],  tid, (const short*)0, false);

        for (int i = tid; i < 768; i += 256)
            g_Tct[i*8 + k] = (i < 729) ? m[PHYS((int)g_tabs.s4of[i])] : 0.f;
    } else {
        const int g    = blk - NPTM;
        const int rowT = g >> 5;            // 0..3 : 64-row tiles
        const int colT = (g >> 3) & 3;      // 0..3 : 64-col tiles
        const int kp   = g & 7;             // 0..7 : 98-K slices
        const int row0 = rowT * 64, col0 = colT * 64;

        float* ws = reinterpret_cast<float*>(su);            // [64][100]
        float* xs = reinterpret_cast<float*>(su + 25600);    // [64][100]

        const float2* W1_2 = reinterpret_cast<const float2*>(W1);
        const float2* x_2  = reinterpret_cast<const float2*>(x);
        const int kof = kp * 49;            // in float2 units

        for (int idx = tid; idx < 64*49; idx += 256) {
            int c = idx / 49, j2 = idx - c*49;
            float2 wv = W1_2[(col0 + c)*392 + kof + j2];
            ws[c*100 + 2*j2]     = wv.x;
            ws[c*100 + 2*j2 + 1] = wv.y;
            float2 xv = x_2[(row0 + c)*392 + kof + j2];
            xs[c*100 + 2*j2]     = xv.x;
            xs[c*100 + 2*j2 + 1] = xv.y;
        }
        if (tid < 128) {
            int c = tid >> 1, o = 98 + (tid & 1);
            ws[c*100 + o] = 0.f;
            xs[c*100 + o] = 0.f;
        }
        __syncthreads();

        const ulonglong2* wA = reinterpret_cast<const ulonglong2*>(ws + lane*100);
        const ulonglong2* wB = reinterpret_cast<const ulonglong2*>(ws + (lane + 32)*100);
        const float* xrow = xs + (wrp * 8) * 100;

        u64 acc[8][2];
#pragma unroll
        for (int r = 0; r < 8; r++) { acc[r][0] = 0ull; acc[r][1] = 0ull; }

#pragma unroll 5
        for (int j = 0; j < 25; j++) {
            ulonglong2 wa = wA[j];
            ulonglong2 wb = wB[j];
#pragma unroll
            for (int r = 0; r < 8; r++) {
                ulonglong2 xv = *reinterpret_cast<const ulonglong2*>(xrow + r*100 + 4*j);
                ffma2(acc[r][0], xv.x, wa.x);
                ffma2(acc[r][0], xv.y, wa.y);
                ffma2(acc[r][1], xv.x, wb.x);
                ffma2(acc[r][1], xv.y, wb.y);
            }
        }
#pragma unroll
        for (int r = 0; r < 8; r++) {
            int row = row0 + wrp*8 + r;
            float2 a0 = *reinterpret_cast<float2*>(&acc[r][0]);
            float2 a1 = *reinterpret_cast<float2*>(&acc[r][1]);
            g_hp[kp*65536 + row*256 + col0 + lane]      = a0.x + a0.y;
            g_hp[kp*65536 + row*256 + col0 + 32 + lane] = a1.x + a1.y;
        }
    }
#if __CUDA_ARCH__ >= 900
    cudaTriggerProgrammaticLaunchCompletion();
#endif
}

// ---------- kernel 2 (PDL secondary): 4 rows/block ----------
__device__ __forceinline__ float pick3(int d, float vx, float vz) {
    return (d == 0) ? 1.f : ((d == 1) ? vx : vz);
}

__global__ void __launch_bounds__(256) k2(const float* __restrict__ b1v,
                                          const float* __restrict__ lng, const float* __restrict__ lnb,
                                          const float* __restrict__ W2, const float* __restrict__ b2,
                                          const float* __restrict__ Wp, const float* __restrict__ bp,
                                          float* __restrict__ out)
{
    __shared__ float4 red[8][2];
    __shared__ float hn[4][HID];
    __shared__ float pw[24];
    __shared__ float plo[4][27], phi[4][27];
    __shared__ float r6[8][24];

    const int tid = threadIdx.x;
    const int lane = tid & 31, w = tid >> 5;
    const int r0 = blockIdx.x * 4;

    // ---- k1-independent prefetch / L1 warm (overlaps k1 under PDL) ----
    const float pb1 = b1v[tid], pg = lng[tid], pbb = lnb[tid];
    float wtouch = 0.f;
#pragma unroll
    for (int i = 0; i < 6; i++) wtouch += W2[i*256 + tid];
    if (tid < 12) wtouch += Wp[tid];
    if (tid < 6)  wtouch += b2[tid];
    if (tid < 2)  wtouch += bp[tid];

#if __CUDA_ARCH__ >= 900
    cudaGridDependencySynchronize();
#endif

    // ---- k1-dependent ----
    const float4* Tct4 = reinterpret_cast<const float4*>(g_Tct);
    float4 tA[3], tB[3];
#pragma unroll
    for (int j = 0; j < 3; j++) {
        int ss = tid + j * 256;
        tA[j] = Tct4[ss*2];
        tB[j] = Tct4[ss*2 + 1];
    }

    float h[4];
#pragma unroll
    for (int r = 0; r < 4; r++) {
        float v = pb1;
#pragma unroll
        for (int p = 0; p < KS; p++) v += g_hp[p*65536 + (r0 + r)*256 + tid];
        h[r] = fmaxf(v, 0.f);
    }

    // phase 1: fused sum+sumsq for 4 rows
    float s[4], q[4];
#pragma unroll
    for (int r = 0; r < 4; r++) { s[r] = h[r]; q[r] = h[r]*h[r]; }
#pragma unroll
    for (int o = 16; o > 0; o >>= 1) {
#pragma unroll
        for (int r = 0; r < 4; r++) {
            s[r] += __shfl_down_sync(~0u, s[r], o);
            q[r] += __shfl_down_sync(~0u, q[r], o);
        }
    }
    if (lane == 0) {
        red[w][0] = make_float4(s[0], q[0], s[1], q[1]);
        red[w][1] = make_float4(s[2], q[2], s[3], q[3]);
    }
    __syncthreads();
    float4 R01 = red[0][0], R23 = red[0][1];
#pragma unroll
    for (int i = 1; i < 8; i++) {
        float4 a = red[i][0], b = red[i][1];
        R01.x += a.x; R01.y += a.y; R01.z += a.z; R01.w += a.w;
        R23.x += b.x; R23.y += b.y; R23.z += b.z; R23.w += b.w;
    }
    float mu[4], rs[4];
    mu[0] = R01.x*(1.f/256.f); rs[0] = rsqrtf(R01.y*(1.f/256.f) - mu[0]*mu[0] + 1e-5f);
    mu[1] = R01.z*(1.f/256.f); rs[1] = rsqrtf(R01.w*(1.f/256.f) - mu[1]*mu[1] + 1e-5f);
    mu[2] = R23.x*(1.f/256.f); rs[2] = rsqrtf(R23.y*(1.f/256.f) - mu[2]*mu[2] + 1e-5f);
    mu[3] = R23.z*(1.f/256.f); rs[3] = rsqrtf(R23.w*(1.f/256.f) - mu[3]*mu[3] + 1e-5f);
#pragma unroll
    for (int r = 0; r < 4; r++)
        hn[r][tid] = (h[r] - mu[r]) * rs[r] * pg + pbb;
    __syncthreads();

    // phase 2: 24 dot products (obs x row), 3 per warp
#pragma unroll
    for (int t = 0; t < 3; t++) {
        int d = w + t*8;           // 0..23
        int o = d >> 2, r = d & 3;
        float acc = 0.f;
#pragma unroll
        for (int j = 0; j < 8; j++)
            acc = fmaf(hn[r][lane + 32*j], W2[o*256 + lane + 32*j], acc);
#pragma unroll
        for (int of = 16; of > 0; of >>= 1) acc += __shfl_down_sync(~0u, acc, of);
        if (lane == 0) pw[d] = acc;
    }
    __syncthreads();

    // phase 3: warps 0..3 handle row w: z -> Bloch -> half-products
    if (w < 4) {
        float pv = (lane < 6) ? (pw[lane*4 + w] + b2[lane]) : 0.f;
        float z = tanhf(pv);
        float sn, cn;
        sincosf(PI_F * z, &sn, &cn);
        float tx = LAM1 * sn, tz = LAM1 * cn;
        float txs[6], tzs[6];
#pragma unroll
        for (int q2 = 0; q2 < 6; q2++) {
            txs[q2] = __shfl_sync(~0u, tx, q2);
            tzs[q2] = __shfl_sync(~0u, tz, q2);
        }
        if (lane < 27) {
            int d0 = lane % 3, d1 = (lane / 3) % 3, d2 = lane / 9;
            plo[w][lane] = pick3(d0, txs[0], tzs[0]) * pick3(d1, txs[1], tzs[1]) * pick3(d2, txs[2], tzs[2]);
            phi[w][lane] = pick3(d0, txs[3], tzs[3]) * pick3(d1, txs[4], tzs[4]) * pick3(d2, txs[5], tzs[5]);
        }
    }
    __syncthreads();

    // phase 4: 729-term eval, 4 rows share the register tables
    float acc[24];
#pragma unroll
    for (int d = 0; d < 24; d++) acc[d] = 0.f;
#pragma unroll
    for (int j = 0; j < 3; j++) {
        int ss = tid + j * 256;
        int sc = (ss < 729) ? ss : 0;      // padded table rows are zero
        int lo = sc % 27, hi = sc / 27;
        float4 ta = tA[j], tb = tB[j];
#pragma unroll
        for (int r = 0; r < 4; r++) {
            float pr = plo[r][lo] * phi[r][hi];
            acc[0*4 + r] = fmaf(pr, ta.x, acc[0*4 + r]);
            acc[1*4 + r] = fmaf(pr, ta.y, acc[1*4 + r]);
            acc[2*4 + r] = fmaf(pr, ta.z, acc[2*4 + r]);
            acc[3*4 + r] = fmaf(pr, ta.w, acc[3*4 + r]);
            acc[4*4 + r] = fmaf(pr, tb.x, acc[4*4 + r]);
            acc[5*4 + r] = fmaf(pr, tb.y, acc[5*4 + r]);
        }
    }
#pragma unroll
    for (int d = 0; d < 24; d++) {
#pragma unroll
        for (int o = 16; o > 0; o >>= 1)
            acc[d] += __shfl_down_sync(~0u, acc[d], o);
    }
    if (lane == 0) {
#pragma unroll
        for (int d = 0; d < 24; d++) r6[w][d] = acc[d];
    }
    __syncthreads();

    // final: 8 threads -> 4 rows x 2 outputs
    if (tid < 8) {
        int r = tid >> 1, c = tid & 1;
        float o = bp[c];
#pragma unroll
        for (int k = 0; k < 6; k++) {
            float ev = 0.f;
#pragma unroll
            for (int ww = 0; ww < 8; ww++) ev += r6[ww][k*4 + r];
            o = fmaf(ev, Wp[c*6 + k], o);
        }
        out[(r0 + r)*2 + c] = o;
    }
    if (wtouch == 1.2345e30f) out[0] = wtouch;   // keep prefetch loads live (never true)
}

extern "C" void kernel_launch(void* const* d_in, const int* in_sizes, int n_in,
                              void* d_out, int out_size)
{
    const float* x        = (const float*)d_in[0];
    const float* W1       = (const float*)d_in[1];
    const float* b1       = (const float*)d_in[2];
    const float* ln_g     = (const float*)d_in[3];
    const float* ln_b     = (const float*)d_in[4];
    const float* W2       = (const float*)d_in[5];
    const float* b2       = (const float*)d_in[6];
    const float* shared_w = (const float*)d_in[7];
    const float* task_w   = (const float*)d_in[8];
    const float* Wp       = (const float*)d_in[9];
    const float* bp       = (const float*)d_in[10];
    float* out = (float*)d_out;

    cudaFuncSetAttribute(k1, cudaFuncAttributeMaxDynamicSharedMemorySize, SMEM_DYN);

    k1<<<NPTM + GEMM_BLOCKS, 256, SMEM_DYN>>>(x, W1, shared_w, task_w);

    cudaLaunchConfig_t cfg = {};
    cfg.gridDim  = dim3(BATCH / 4, 1, 1);
    cfg.blockDim = dim3(256, 1, 1);
    cfg.dynamicSmemBytes = 0;
    cudaLaunchAttribute attrs[1];
    attrs[0].id = cudaLaunchAttributeProgrammaticStreamSerialization;
    attrs[0].val.programmaticStreamSerializationAllowed = 1;
    cfg.attrs = attrs;
    cfg.numAttrs = 1;
    cudaLaunchKernelEx(&cfg, k2, b1, ln_g, ln_b, W2, b2, Wp, bp, out);
}